// round 13
// baseline (speedup 1.0000x reference)
#include <cuda_runtime.h>
#include <cuda_fp16.h>
#include <cstdint>

#define Bq    16
#define Cdim  384
#define Ndim  4096
#define NH    8
#define HD    48
#define OC    1152
#define TOK   65536

// Scratch (__device__ globals: allocation-free rule)
__device__ __half g_xh[(size_t)Bq * Cdim * Ndim];  // fp16 copy of x  [B][C][N]
__device__ __half g_wq[OC * Cdim];                 // fp16 qkv_w
__device__ __half g_wp[Cdim * Cdim];               // fp16 proj_w
__device__ __half g_attn[(size_t)TOK * Cdim];      // [tokens][C]

// ---------------------------------------------------------------------------
// helpers
// ---------------------------------------------------------------------------
__device__ __forceinline__ uint32_t smem_u32(const void* p) {
    uint32_t a; asm("{ .reg .u64 t; cvta.to.shared.u64 t, %1; cvt.u32.u64 %0, t; }" : "=r"(a) : "l"(p));
    return a;
}
__device__ __forceinline__ void ldsm4(uint32_t* r, uint32_t addr) {
    asm volatile("ldmatrix.sync.aligned.m8n8.x4.shared.b16 {%0,%1,%2,%3}, [%4];"
                 : "=r"(r[0]), "=r"(r[1]), "=r"(r[2]), "=r"(r[3]) : "r"(addr));
}
__device__ __forceinline__ void ldsm4t(uint32_t* r, uint32_t addr) {
    asm volatile("ldmatrix.sync.aligned.m8n8.x4.trans.shared.b16 {%0,%1,%2,%3}, [%4];"
                 : "=r"(r[0]), "=r"(r[1]), "=r"(r[2]), "=r"(r[3]) : "r"(addr));
}
__device__ __forceinline__ void mma_f16(float* d, const uint32_t* a, const uint32_t b0,
                                        const uint32_t b1) {
    asm volatile("mma.sync.aligned.m16n8k16.row.col.f32.f16.f16.f32 "
                 "{%0,%1,%2,%3}, {%4,%5,%6,%7}, {%8,%9}, {%0,%1,%2,%3};"
                 : "+f"(d[0]), "+f"(d[1]), "+f"(d[2]), "+f"(d[3])
                 : "r"(a[0]), "r"(a[1]), "r"(a[2]), "r"(a[3]), "r"(b0), "r"(b1));
}
__device__ __forceinline__ uint32_t sw128r(int row, int chunk) {
    return (uint32_t)(row * 128 + ((chunk ^ (row & 7)) << 4));
}
__device__ __forceinline__ uint32_t pack2(float x, float y) {
    uint32_t r;
    asm("cvt.rn.f16x2.f32 %0, %1, %2;" : "=r"(r) : "f"(y), "f"(x));
    return r;
}
#define CP_ASYNC16(dst, src) \
    asm volatile("cp.async.cg.shared.global [%0], [%1], 16;" :: "r"(dst), "l"(src))
#define CP_COMMIT() asm volatile("cp.async.commit_group;" ::: "memory")
#define CP_WAIT1()  asm volatile("cp.async.wait_group 1;" ::: "memory")
#define CP_WAIT0()  asm volatile("cp.async.wait_group 0;" ::: "memory")

// ---------------------------------------------------------------------------
// Kernel 0: fp32 -> fp16 conversion of x, qkv_w, proj_w
// ---------------------------------------------------------------------------
__global__ __launch_bounds__(256) void cvt_inputs(const float* __restrict__ x,
                                                  const float* __restrict__ wq,
                                                  const float* __restrict__ wp) {
    const size_t N4x = (size_t)Bq * Cdim * Ndim / 4;
    const size_t N4q = (size_t)OC * Cdim / 4;
    const size_t N4p = (size_t)Cdim * Cdim / 4;
    size_t i = (size_t)blockIdx.x * 256 + threadIdx.x;
    if (i < N4x) {
        float4 v = ((const float4*)x)[i];
        ((uint2*)g_xh)[i] = make_uint2(pack2(v.x, v.y), pack2(v.z, v.w));
    } else if (i < N4x + N4q) {
        size_t j = i - N4x;
        float4 v = ((const float4*)wq)[j];
        ((uint2*)g_wq)[j] = make_uint2(pack2(v.x, v.y), pack2(v.z, v.w));
    } else if (i < N4x + N4q + N4p) {
        size_t j = i - N4x - N4q;
        float4 v = ((const float4*)wp)[j];
        ((uint2*)g_wp)[j] = make_uint2(pack2(v.x, v.y), pack2(v.z, v.w));
    }
}

// ---------------------------------------------------------------------------
// Kernel 1 (FUSED): per-CTA = one 64-token chunk. 256 thr (8 warps).
// Phase A: 3 sweeps x GEMM [384ch x 64tok x 384k]; warp w owns 48 ch = head w's
//          Q (sweep0) / K (sweep1) / V (sweep2), written to warp-private smem.
// Phase B: per-warp attention for head w; P stays in registers.
// Smem: A0@0 (384x80B=30720), A1@30720, X0@61440 (4KB), X1@65536,
//       QKV@69632 (8 warps x 18432B: [sel3][d48][tok64]).  Total 217088.
// ---------------------------------------------------------------------------
#define SM_A0   0u
#define SM_X0   61440u
#define SM_QKV  69632u

__global__ __launch_bounds__(256) void qkv_attn_fused() {
    extern __shared__ char smem[];
    const uint32_t sbase = smem_u32(smem);
    const int tid = threadIdx.x, lane = tid & 31, w = tid >> 5;
    const int blk = blockIdx.x;
    const int b = blk >> 6, nc = blk & 63;
    const int n0 = nc * 64;
    const __half* xb = g_xh + (size_t)b * Cdim * Ndim;

    const int aRowL = ((lane >> 3) & 1) * 8 + (lane & 7);
    const int ldCh = lane >> 4;
    const int gid = lane >> 2, tig = lane & 3;

    float acc[3][8][4];
#pragma unroll
    for (int i = 0; i < 3; i++)
#pragma unroll
        for (int j = 0; j < 8; j++)
#pragma unroll
            for (int q = 0; q < 4; q++) acc[i][j][q] = 0.f;

    // fill one BK=32 k-tile: A = weights [384ch x 32k] rows 80B; X = x [32k x 64tok]
    auto fillT = [&](int t) {
        const int s = t & 1;
        const int sweep = t / 12;
        const int kt = (t % 12) * 32;
        const uint32_t A = sbase + SM_A0 + (uint32_t)s * 30720u;
#pragma unroll
        for (int u = 0; u < 6; u++) {
            int idx = tid + u * 256;            // 0..1535
            int row = idx >> 2, c = idx & 3;
            CP_ASYNC16(A + (uint32_t)(row * 80 + (c << 4)),
                       g_wq + (size_t)(sweep * 384 + row) * Cdim + kt + c * 8);
        }
        const uint32_t X = sbase + SM_X0 + (uint32_t)s * 4096u;
        {
            int row = tid >> 3, c8 = tid & 7;   // 32 rows x 8 chunks
            CP_ASYNC16(X + sw128r(row, c8),
                       xb + (size_t)(kt + row) * Ndim + n0 + c8 * 8);
        }
        CP_COMMIT();
    };

    fillT(0);
    for (int it = 0; it < 36; it++) {
        CP_WAIT0();
        __syncthreads();                        // stage it&1 visible; stage (it+1)&1 free
        if (it + 1 < 36) fillT(it + 1);
        {
            const uint32_t Ast = sbase + SM_A0 + (uint32_t)(it & 1) * 30720u;
            const uint32_t Xst = sbase + SM_X0 + (uint32_t)(it & 1) * 4096u;
#pragma unroll
            for (int ks = 0; ks < 2; ks++) {
                uint32_t a[3][4], bf[4][4];
#pragma unroll
                for (int mt = 0; mt < 3; mt++)
                    ldsm4(a[mt], Ast + (uint32_t)((w * 48 + mt * 16 + aRowL) * 80) +
                                  (uint32_t)((ks * 2 + ldCh) << 4));
#pragma unroll
                for (int p = 0; p < 4; p++)
                    ldsm4t(bf[p], Xst + sw128r(ks * 16 + aRowL, p * 2 + ldCh));
#pragma unroll
                for (int mt = 0; mt < 3; mt++)
#pragma unroll
                    for (int p = 0; p < 4; p++) {
                        mma_f16(acc[mt][2 * p],     a[mt], bf[p][0], bf[p][1]);
                        mma_f16(acc[mt][2 * p + 1], a[mt], bf[p][2], bf[p][3]);
                    }
            }
        }
        if ((it % 12) == 11) {
            // sweep epilogue: warp-private store [sel][d48][tok64] (fp16, swizzled)
            const int sel = it / 12;
            char* reg0 = smem + SM_QKV + w * 18432 + sel * 6144;
#pragma unroll
            for (int mt = 0; mt < 3; mt++) {
                int d0 = mt * 16 + gid;
#pragma unroll
                for (int nt = 0; nt < 8; nt++) {
                    *(uint32_t*)(reg0 + sw128r(d0, nt) + tig * 4) =
                        pack2(acc[mt][nt][0], acc[mt][nt][1]);
                    *(uint32_t*)(reg0 + sw128r(d0 + 8, nt) + tig * 4) =
                        pack2(acc[mt][nt][2], acc[mt][nt][3]);
                }
            }
#pragma unroll
            for (int i = 0; i < 3; i++)
#pragma unroll
                for (int j = 0; j < 8; j++)
#pragma unroll
                    for (int q = 0; q < 4; q++) acc[i][j][q] = 0.f;
        }
    }
    __syncwarp();

    // -------- Phase B: attention for head w (warp-local, no block barriers) ----
    const uint32_t Qr = sbase + SM_QKV + (uint32_t)w * 18432u;
    const uint32_t Kr = Qr + 6144u;
    const uint32_t Vr = Qr + 12288u;
    const size_t m0 = (size_t)b * Ndim + nc * 64;
    const float scale = 0.14433756729740643f;   // 1/sqrt(48)

#pragma unroll
    for (int rb = 0; rb < 4; rb++) {
        // S = Q @ K^T for token rows rb*16..rb*16+15 (m16 x n64 x k48)
        float s[8][4];
#pragma unroll
        for (int j = 0; j < 8; j++)
#pragma unroll
            for (int q = 0; q < 4; q++) s[j][q] = 0.f;
#pragma unroll
        for (int ks = 0; ks < 3; ks++) {
            uint32_t ar[4], a[4], kb[4][4];
            int drow = ks * 16 + aRowL;
            ldsm4t(ar, Qr + sw128r(drow, rb * 2 + ldCh));
            a[0] = ar[0]; a[1] = ar[2]; a[2] = ar[1]; a[3] = ar[3];
#pragma unroll
            for (int p = 0; p < 4; p++)
                ldsm4t(kb[p], Kr + sw128r(drow, p * 2 + ldCh));
#pragma unroll
            for (int p = 0; p < 4; p++) {
                mma_f16(s[2 * p],     a, kb[p][0], kb[p][1]);
                mma_f16(s[2 * p + 1], a, kb[p][2], kb[p][3]);
            }
        }
        // softmax over 64 cols (rows gid, gid+8 within this m16)
        float i0, i1;
        {
            float m0v = -1e30f, m1v = -1e30f;
#pragma unroll
            for (int nt = 0; nt < 8; nt++) {
#pragma unroll
                for (int q = 0; q < 4; q++) s[nt][q] *= scale;
                m0v = fmaxf(m0v, fmaxf(s[nt][0], s[nt][1]));
                m1v = fmaxf(m1v, fmaxf(s[nt][2], s[nt][3]));
            }
#pragma unroll
            for (int o = 1; o <= 2; o <<= 1) {
                m0v = fmaxf(m0v, __shfl_xor_sync(~0u, m0v, o));
                m1v = fmaxf(m1v, __shfl_xor_sync(~0u, m1v, o));
            }
            float s0 = 0.f, s1 = 0.f;
#pragma unroll
            for (int nt = 0; nt < 8; nt++) {
                s[nt][0] = __expf(s[nt][0] - m0v); s[nt][1] = __expf(s[nt][1] - m0v);
                s[nt][2] = __expf(s[nt][2] - m1v); s[nt][3] = __expf(s[nt][3] - m1v);
                s0 += s[nt][0] + s[nt][1]; s1 += s[nt][2] + s[nt][3];
            }
#pragma unroll
            for (int o = 1; o <= 2; o <<= 1) {
                s0 += __shfl_xor_sync(~0u, s0, o);
                s1 += __shfl_xor_sync(~0u, s1, o);
            }
            i0 = 1.f / s0; i1 = 1.f / s1;
        }
        // O = P @ V (m16 x n48 x k64); P built in-register from s (A-frag layout)
        float o[6][4];
#pragma unroll
        for (int j = 0; j < 6; j++)
#pragma unroll
            for (int q = 0; q < 4; q++) o[j][q] = 0.f;
#pragma unroll
        for (int ks = 0; ks < 4; ks++) {
            uint32_t aP[4], vb[3][4];
            aP[0] = pack2(s[2 * ks][0] * i0,     s[2 * ks][1] * i0);
            aP[1] = pack2(s[2 * ks][2] * i1,     s[2 * ks][3] * i1);
            aP[2] = pack2(s[2 * ks + 1][0] * i0, s[2 * ks + 1][1] * i0);
            aP[3] = pack2(s[2 * ks + 1][2] * i1, s[2 * ks + 1][3] * i1);
#pragma unroll
            for (int p = 0; p < 3; p++)
                ldsm4(vb[p], Vr + sw128r(p * 16 + aRowL, ks * 2 + ldCh));
#pragma unroll
            for (int p = 0; p < 3; p++) {
                mma_f16(o[2 * p],     aP, vb[p][0], vb[p][2]);
                mma_f16(o[2 * p + 1], aP, vb[p][1], vb[p][3]);
            }
        }
        // store O to g_attn [tok][C], head columns w*48..
        {
            const int r0 = rb * 16 + gid;
#pragma unroll
            for (int nt = 0; nt < 6; nt++) {
                int col = w * HD + nt * 8 + tig * 2;
                *(uint32_t*)(&g_attn[(m0 + r0) * Cdim + col])     = pack2(o[nt][0], o[nt][1]);
                *(uint32_t*)(&g_attn[(m0 + r0 + 8) * Cdim + col]) = pack2(o[nt][2], o[nt][3]);
            }
        }
    }
}

// ---------------------------------------------------------------------------
// Kernel 3: out[b][c][n] = sum_k g_wp[c][k] * g_attn[tok][k] + bias[c]
// 128 thr, warp tile 64x64 (2x2), cp.async 3-stage.  (unchanged, best known)
// ---------------------------------------------------------------------------
__global__ __launch_bounds__(128, 2) void proj_mma(const float* __restrict__ bias,
                                                   float* __restrict__ out) {
    extern __shared__ char smem[];
    const uint32_t sbase = smem_u32(smem);
    const int tid = threadIdx.x, lane = tid & 31, wid = tid >> 5;
    const int warp_m = wid >> 1, warp_n = wid & 1;
    const int j0 = blockIdx.x * 128;
    const int tok0 = blockIdx.y * 128;

    const int aRowL = ((lane >> 3) & 1) * 8 + (lane & 7);
    const int ldCh = lane >> 4;
    int aRow[4], bRow[4];
#pragma unroll
    for (int mt = 0; mt < 4; mt++) aRow[mt] = warp_m * 64 + mt * 16 + aRowL;
#pragma unroll
    for (int p = 0; p < 4; p++)    bRow[p] = warp_n * 64 + p * 16 + aRowL;

    float acc[4][8][4];
#pragma unroll
    for (int i = 0; i < 4; i++)
#pragma unroll
        for (int j = 0; j < 8; j++)
#pragma unroll
            for (int q = 0; q < 4; q++) acc[i][j][q] = 0.f;

    const int fR = tid >> 3, fC = tid & 7;
    auto fill = [&](int s, int t) {
        const int kt = t * 64;
        const uint32_t A = sbase + (uint32_t)s * 32768u;
        const uint32_t B = A + 16384u;
#pragma unroll
        for (int u = 0; u < 8; u++) {
            int row = fR + u * 16;
            CP_ASYNC16(A + sw128r(row, fC), g_wp + (size_t)(j0 + row) * Cdim + kt + fC * 8);
            CP_ASYNC16(B + sw128r(row, fC),
                       g_attn + (size_t)(tok0 + row) * Cdim + kt + fC * 8);
        }
        CP_COMMIT();
    };

    fill(0, 0);
    fill(1, 1);

    for (int it = 0; it < 6; it++) {
        if (it < 5) CP_WAIT1(); else CP_WAIT0();
        __syncthreads();
        {
            const uint32_t bA = sbase + (uint32_t)(it % 3) * 32768u;
            const uint32_t bB = bA + 16384u;
#pragma unroll
            for (int ks = 0; ks < 4; ks++) {
                uint32_t a[4][4], b[4][4];
#pragma unroll
                for (int mt = 0; mt < 4; mt++)
                    ldsm4(a[mt], bA + sw128r(aRow[mt], ks * 2 + ldCh));
#pragma unroll
                for (int p = 0; p < 4; p++)
                    ldsm4(b[p], bB + sw128r(bRow[p], ks * 2 + ldCh));
#pragma unroll
                for (int mt = 0; mt < 4; mt++)
#pragma unroll
                    for (int p = 0; p < 4; p++) {
                        mma_f16(acc[mt][2 * p],     a[mt], b[p][0], b[p][2]);
                        mma_f16(acc[mt][2 * p + 1], a[mt], b[p][1], b[p][3]);
                    }
            }
        }
        if (it + 2 < 6) fill((it + 2) % 3, it + 2);
    }

    const int gid = lane >> 2, tig = lane & 3;
    float* outb = out + (size_t)(tok0 >> 12) * Cdim * Ndim;
    const int nb = (tok0 & 4095) + warp_n * 64 + 2 * tig;
#pragma unroll
    for (int mt = 0; mt < 4; mt++) {
        int r = j0 + warp_m * 64 + mt * 16 + gid;
        float bi0 = __ldg(&bias[r]), bi1 = __ldg(&bias[r + 8]);
#pragma unroll
        for (int nt = 0; nt < 8; nt++) {
            int cc = nb + nt * 8;
            *(float2*)(&outb[(size_t)r * Ndim + cc]) =
                make_float2(acc[mt][nt][0] + bi0, acc[mt][nt][1] + bi0);
            *(float2*)(&outb[(size_t)(r + 8) * Ndim + cc]) =
                make_float2(acc[mt][nt][2] + bi1, acc[mt][nt][3] + bi1);
        }
    }
}

// ---------------------------------------------------------------------------
extern "C" void kernel_launch(void* const* d_in, const int* in_sizes, int n_in,
                              void* d_out, int out_size) {
    const float* x      = (const float*)d_in[0];
    const float* qkv_w  = (const float*)d_in[1];
    const float* proj_w = (const float*)d_in[2];
    const float* proj_b = (const float*)d_in[3];
    float* out = (float*)d_out;

    const int smem_fused = 217088;  // A 2x30720 + X 2x4096 + QKV 147456
    const int smem_gemm  = 98304;   // 3 stages x 32KB
    cudaFuncSetAttribute(qkv_attn_fused, cudaFuncAttributeMaxDynamicSharedMemorySize, smem_fused);
    cudaFuncSetAttribute(proj_mma, cudaFuncAttributeMaxDynamicSharedMemorySize, smem_gemm);

    const size_t n4 = (size_t)Bq * Cdim * Ndim / 4 + (size_t)OC * Cdim / 4
                    + (size_t)Cdim * Cdim / 4;
    cvt_inputs<<<(int)((n4 + 255) / 256), 256>>>(x, qkv_w, proj_w);
    qkv_attn_fused<<<Bq * 64, 256, smem_fused>>>();
    proj_mma<<<dim3(3, 512), 128, smem_gemm>>>(proj_b, out);
}

// round 15
// speedup vs baseline: 1.3035x; 1.3035x over previous
#include <cuda_runtime.h>
#include <cuda_fp16.h>
#include <cstdint>

#define Bq    16
#define Cdim  384
#define Ndim  4096
#define NH    8
#define HD    48
#define OC    1152
#define TOK   65536

// Scratch (__device__ globals: allocation-free rule)
__device__ __half g_xh[(size_t)Bq * Cdim * Ndim];  // fp16 copy of x  [B][C][N]
__device__ __half g_wq[OC * Cdim];                 // fp16 qkv_w
__device__ __half g_wp[Cdim * Cdim];               // fp16 proj_w
// blocked qkv: [(b*64+nc)*8+h][sel(3)][d(48)][tok64] — 18KB contiguous per attn block
__device__ __half g_qkvB[(size_t)Bq * 64 * NH * 3 * HD * 64];
__device__ __half g_attn[(size_t)TOK * Cdim];      // [tokens][C]

// ---------------------------------------------------------------------------
// helpers
// ---------------------------------------------------------------------------
__device__ __forceinline__ uint32_t smem_u32(const void* p) {
    uint32_t a; asm("{ .reg .u64 t; cvta.to.shared.u64 t, %1; cvt.u32.u64 %0, t; }" : "=r"(a) : "l"(p));
    return a;
}
__device__ __forceinline__ void ldsm4(uint32_t* r, uint32_t addr) {
    asm volatile("ldmatrix.sync.aligned.m8n8.x4.shared.b16 {%0,%1,%2,%3}, [%4];"
                 : "=r"(r[0]), "=r"(r[1]), "=r"(r[2]), "=r"(r[3]) : "r"(addr));
}
__device__ __forceinline__ void ldsm4t(uint32_t* r, uint32_t addr) {
    asm volatile("ldmatrix.sync.aligned.m8n8.x4.trans.shared.b16 {%0,%1,%2,%3}, [%4];"
                 : "=r"(r[0]), "=r"(r[1]), "=r"(r[2]), "=r"(r[3]) : "r"(addr));
}
__device__ __forceinline__ void mma_f16(float* d, const uint32_t* a, const uint32_t b0,
                                        const uint32_t b1) {
    asm volatile("mma.sync.aligned.m16n8k16.row.col.f32.f16.f16.f32 "
                 "{%0,%1,%2,%3}, {%4,%5,%6,%7}, {%8,%9}, {%0,%1,%2,%3};"
                 : "+f"(d[0]), "+f"(d[1]), "+f"(d[2]), "+f"(d[3])
                 : "r"(a[0]), "r"(a[1]), "r"(a[2]), "r"(a[3]), "r"(b0), "r"(b1));
}
__device__ __forceinline__ uint32_t sw128r(int row, int chunk) {
    return (uint32_t)(row * 128 + ((chunk ^ (row & 7)) << 4));
}
__device__ __forceinline__ uint32_t sw256r(int row, int chunk) {
    return (uint32_t)(row * 256 + ((chunk ^ (row & 7)) << 4));
}
__device__ __forceinline__ uint32_t pack2(float x, float y) {
    uint32_t r;
    asm("cvt.rn.f16x2.f32 %0, %1, %2;" : "=r"(r) : "f"(y), "f"(x));
    return r;
}
#define CP_ASYNC16(dst, src) \
    asm volatile("cp.async.cg.shared.global [%0], [%1], 16;" :: "r"(dst), "l"(src))
#define CP_COMMIT() asm volatile("cp.async.commit_group;" ::: "memory")
#define CP_WAIT1()  asm volatile("cp.async.wait_group 1;" ::: "memory")
#define CP_WAIT0()  asm volatile("cp.async.wait_group 0;" ::: "memory")

// ---------------------------------------------------------------------------
// Kernel 0: fp32 -> fp16 conversion of x, qkv_w, proj_w
// ---------------------------------------------------------------------------
__global__ __launch_bounds__(256) void cvt_inputs(const float* __restrict__ x,
                                                  const float* __restrict__ wq,
                                                  const float* __restrict__ wp) {
    const size_t N4x = (size_t)Bq * Cdim * Ndim / 4;
    const size_t N4q = (size_t)OC * Cdim / 4;
    const size_t N4p = (size_t)Cdim * Cdim / 4;
    size_t i = (size_t)blockIdx.x * 256 + threadIdx.x;
    if (i < N4x) {
        float4 v = ((const float4*)x)[i];
        ((uint2*)g_xh)[i] = make_uint2(pack2(v.x, v.y), pack2(v.z, v.w));
    } else if (i < N4x + N4q) {
        size_t j = i - N4x;
        float4 v = ((const float4*)wq)[j];
        ((uint2*)g_wq)[j] = make_uint2(pack2(v.x, v.y), pack2(v.z, v.w));
    } else if (i < N4x + N4q + N4p) {
        size_t j = i - N4x - N4q;
        float4 v = ((const float4*)wp)[j];
        ((uint2*)g_wp)[j] = make_uint2(pack2(v.x, v.y), pack2(v.z, v.w));
    }
}

// ---------------------------------------------------------------------------
// Kernel 1: qkv GEMM -> blocked layout g_qkvB.
// 128 thr, CTA tile 96(ch) x 128(tok), BK=32, warp tile 48x64 (2x2),
// cp.async 3-stage, target 3 CTAs/SM (12 warps).
// A smem: 96 rows x 32k fp16, 80B-padded rows, 7680B.
// B smem: 32k x 128tok fp16, 256B swizzled rows (16 chunks!), 8192B.
// Stage = 15872B.
// ---------------------------------------------------------------------------
#define QKV_STAGE 15872u
__global__ __launch_bounds__(128, 3) void qkv_mma() {
    extern __shared__ char smem[];
    const uint32_t sbase = smem_u32(smem);
    const int tid = threadIdx.x, lane = tid & 31, wid = tid >> 5;
    const int warp_m = wid >> 1, warp_n = wid & 1;
    const int j0 = blockIdx.x * 96;
    const int tok0 = blockIdx.y * 128;
    const int n0 = tok0 & 4095;
    const __half* xb = g_xh + (size_t)(tok0 >> 12) * Cdim * Ndim;

    const int aRowL = ((lane >> 3) & 1) * 8 + (lane & 7);
    const int ldCh = lane >> 4;

    float acc[3][8][4];
#pragma unroll
    for (int i = 0; i < 3; i++)
#pragma unroll
        for (int j = 0; j < 8; j++)
#pragma unroll
            for (int q = 0; q < 4; q++) acc[i][j][q] = 0.f;

    auto fill = [&](int s, int t) {
        const int kt = t * 32;
        const uint32_t A = sbase + (uint32_t)s * QKV_STAGE;
        const uint32_t B = A + 7680u;
#pragma unroll
        for (int u = 0; u < 3; u++) {
            int idx = tid + u * 128;            // 0..383: 96 rows x 4 chunks
            int row = idx >> 2, c = idx & 3;
            CP_ASYNC16(A + (uint32_t)(row * 80 + (c << 4)),
                       g_wq + (size_t)(j0 + row) * Cdim + kt + c * 8);
        }
#pragma unroll
        for (int u = 0; u < 4; u++) {
            int idx = tid + u * 128;            // 0..511: 32 rows x 16 chunks
            int row = idx >> 4, c16 = idx & 15;
            CP_ASYNC16(B + sw256r(row, c16),
                       xb + (size_t)(kt + row) * Ndim + n0 + c16 * 8);
        }
        CP_COMMIT();
    };

    fill(0, 0);
    fill(1, 1);

    for (int it = 0; it < 12; it++) {
        if (it < 11) CP_WAIT1(); else CP_WAIT0();
        __syncthreads();
        {
            const uint32_t A = sbase + (uint32_t)(it % 3) * QKV_STAGE;
            const uint32_t B = A + 7680u;
#pragma unroll
            for (int ks = 0; ks < 2; ks++) {
                uint32_t a[3][4], bf[4][4];
#pragma unroll
                for (int mt = 0; mt < 3; mt++)
                    ldsm4(a[mt], A + (uint32_t)((warp_m * 48 + mt * 16 + aRowL) * 80) +
                                  (uint32_t)((ks * 2 + ldCh) << 4));
#pragma unroll
                for (int p = 0; p < 4; p++)
                    ldsm4t(bf[p], B + sw256r(ks * 16 + aRowL, warp_n * 8 + p * 2 + ldCh));
#pragma unroll
                for (int mt = 0; mt < 3; mt++)
#pragma unroll
                    for (int p = 0; p < 4; p++) {
                        mma_f16(acc[mt][2 * p],     a[mt], bf[p][0], bf[p][1]);
                        mma_f16(acc[mt][2 * p + 1], a[mt], bf[p][2], bf[p][3]);
                    }
            }
        }
        if (it + 2 < 12) fill((it + 2) % 3, it + 2);
    }

    // epilogue: scatter into blocked layout
    const int gid = lane >> 2, tig = lane & 3;
    const int bq  = tok0 >> 12;
    const int ncq = ((tok0 & 4095) >> 6) + warp_n;
    const size_t chunkbase = (size_t)((bq * 64 + ncq) * NH) * (3 * HD * 64);
#pragma unroll
    for (int mt = 0; mt < 3; mt++) {
        int rb = j0 + warp_m * 48 + mt * 16 + gid;
#pragma unroll
        for (int rr2 = 0; rr2 < 2; rr2++) {
            int r = rb + rr2 * 8;
            int sel = r / 384;
            int rm = r - sel * 384;
            int h = rm / 48;
            int d = rm - h * 48;
            size_t rowbase = chunkbase + (size_t)((h * 3 + sel) * (HD * 64) + d * 64);
#pragma unroll
            for (int nt = 0; nt < 8; nt++) {
                int t64 = nt * 8 + 2 * tig;
                *(uint32_t*)(&g_qkvB[rowbase + t64]) =
                    pack2(acc[mt][nt][2 * rr2], acc[mt][nt][2 * rr2 + 1]);
            }
        }
    }
}

// ---------------------------------------------------------------------------
// Kernel 2: block-local attention, fp16 mma. 1 CTA (128 thr) per chunk-block.
// ---------------------------------------------------------------------------
__global__ __launch_bounds__(128) void attn_mma() {
    extern __shared__ char smem[];
    const uint32_t sbase = smem_u32(smem);
    const int tid = threadIdx.x, lane = tid & 31, w = tid >> 5;
    const int blk = blockIdx.x;                 // (b*64+nc)*8 + h
    const int b = blk >> 9, nc = (blk >> 3) & 63, h = blk & 7;
    const size_t m0 = (size_t)b * Ndim + nc * 64;
    const char* gsrc = (const char*)(g_qkvB) + (size_t)blk * (3 * HD * 64 * 2);

#pragma unroll
    for (int u = 0; u < 9; u++) {
        int ci = tid + u * 128;
        int row = ci >> 3, c8 = ci & 7;
        CP_ASYNC16(sbase + sw128r(row, c8), gsrc + (size_t)ci * 16);
    }
    CP_COMMIT(); CP_WAIT0();
    __syncthreads();

    const int aRowL = ((lane >> 3) & 1) * 8 + (lane & 7);
    const int ldCh = lane >> 4;

    float s[8][4];
#pragma unroll
    for (int j = 0; j < 8; j++)
#pragma unroll
        for (int q = 0; q < 4; q++) s[j][q] = 0.f;
#pragma unroll
    for (int ks = 0; ks < 3; ks++) {
        uint32_t ar[4], a[4], kb[4][4];
        int drow = ks * 16 + aRowL;
        ldsm4t(ar, sbase + sw128r(drow, w * 2 + ldCh));
        a[0] = ar[0]; a[1] = ar[2]; a[2] = ar[1]; a[3] = ar[3];
#pragma unroll
        for (int p = 0; p < 4; p++)
            ldsm4t(kb[p], sbase + 6144u + sw128r(drow, p * 2 + ldCh));
#pragma unroll
        for (int p = 0; p < 4; p++) {
            mma_f16(s[2 * p],     a, kb[p][0], kb[p][1]);
            mma_f16(s[2 * p + 1], a, kb[p][2], kb[p][3]);
        }
    }

    const int gid = lane >> 2, tig = lane & 3;
    const float scale = 0.14433756729740643f;
    {
        float m0v = -1e30f, m1v = -1e30f;
#pragma unroll
        for (int nt = 0; nt < 8; nt++) {
#pragma unroll
            for (int q = 0; q < 4; q++) s[nt][q] *= scale;
            m0v = fmaxf(m0v, fmaxf(s[nt][0], s[nt][1]));
            m1v = fmaxf(m1v, fmaxf(s[nt][2], s[nt][3]));
        }
#pragma unroll
        for (int o = 1; o <= 2; o <<= 1) {
            m0v = fmaxf(m0v, __shfl_xor_sync(~0u, m0v, o));
            m1v = fmaxf(m1v, __shfl_xor_sync(~0u, m1v, o));
        }
        float s0 = 0.f, s1 = 0.f;
#pragma unroll
        for (int nt = 0; nt < 8; nt++) {
            s[nt][0] = __expf(s[nt][0] - m0v); s[nt][1] = __expf(s[nt][1] - m0v);
            s[nt][2] = __expf(s[nt][2] - m1v); s[nt][3] = __expf(s[nt][3] - m1v);
            s0 += s[nt][0] + s[nt][1]; s1 += s[nt][2] + s[nt][3];
        }
#pragma unroll
        for (int o = 1; o <= 2; o <<= 1) {
            s0 += __shfl_xor_sync(~0u, s0, o);
            s1 += __shfl_xor_sync(~0u, s1, o);
        }
        float i0 = 1.f / s0, i1 = 1.f / s1;
        const int r0 = w * 16 + gid, r1 = r0 + 8;
        char* Ps = smem + 18432;
#pragma unroll
        for (int nt = 0; nt < 8; nt++) {
            *(uint32_t*)(Ps + sw128r(r0, nt) + tig * 4) = pack2(s[nt][0] * i0, s[nt][1] * i0);
            *(uint32_t*)(Ps + sw128r(r1, nt) + tig * 4) = pack2(s[nt][2] * i1, s[nt][3] * i1);
        }
    }
    __syncwarp();

    float o[6][4];
#pragma unroll
    for (int j = 0; j < 6; j++)
#pragma unroll
        for (int q = 0; q < 4; q++) o[j][q] = 0.f;
#pragma unroll
    for (int ks = 0; ks < 4; ks++) {
        uint32_t a[4], vb[3][4];
        ldsm4(a, sbase + 18432u + sw128r(w * 16 + aRowL, ks * 2 + ldCh));
#pragma unroll
        for (int p = 0; p < 3; p++)
            ldsm4(vb[p], sbase + 12288u + sw128r(p * 16 + aRowL, ks * 2 + ldCh));
#pragma unroll
        for (int p = 0; p < 3; p++) {
            mma_f16(o[2 * p],     a, vb[p][0], vb[p][2]);
            mma_f16(o[2 * p + 1], a, vb[p][1], vb[p][3]);
        }
    }
    {
        const int r0 = w * 16 + gid;
#pragma unroll
        for (int nt = 0; nt < 6; nt++) {
            int col = h * HD + nt * 8 + tig * 2;
            *(uint32_t*)(&g_attn[(m0 + r0) * Cdim + col])     = pack2(o[nt][0], o[nt][1]);
            *(uint32_t*)(&g_attn[(m0 + r0 + 8) * Cdim + col]) = pack2(o[nt][2], o[nt][3]);
        }
    }
}

// ---------------------------------------------------------------------------
// Kernel 3: out[b][c][n] = sum_k g_wp[c][k] * g_attn[tok][k] + bias[c]
// 128 thr, warp tile 64x64 (2x2), cp.async 3-stage.  (unchanged control)
// ---------------------------------------------------------------------------
__global__ __launch_bounds__(128, 2) void proj_mma(const float* __restrict__ bias,
                                                   float* __restrict__ out) {
    extern __shared__ char smem[];
    const uint32_t sbase = smem_u32(smem);
    const int tid = threadIdx.x, lane = tid & 31, wid = tid >> 5;
    const int warp_m = wid >> 1, warp_n = wid & 1;
    const int j0 = blockIdx.x * 128;
    const int tok0 = blockIdx.y * 128;

    const int aRowL = ((lane >> 3) & 1) * 8 + (lane & 7);
    const int ldCh = lane >> 4;
    int aRow[4], bRow[4];
#pragma unroll
    for (int mt = 0; mt < 4; mt++) aRow[mt] = warp_m * 64 + mt * 16 + aRowL;
#pragma unroll
    for (int p = 0; p < 4; p++)    bRow[p] = warp_n * 64 + p * 16 + aRowL;

    float acc[4][8][4];
#pragma unroll
    for (int i = 0; i < 4; i++)
#pragma unroll
        for (int j = 0; j < 8; j++)
#pragma unroll
            for (int q = 0; q < 4; q++) acc[i][j][q] = 0.f;

    const int fR = tid >> 3, fC = tid & 7;
    auto fill = [&](int s, int t) {
        const int kt = t * 64;
        const uint32_t A = sbase + (uint32_t)s * 32768u;
        const uint32_t B = A + 16384u;
#pragma unroll
        for (int u = 0; u < 8; u++) {
            int row = fR + u * 16;
            CP_ASYNC16(A + sw128r(row, fC), g_wp + (size_t)(j0 + row) * Cdim + kt + fC * 8);
            CP_ASYNC16(B + sw128r(row, fC),
                       g_attn + (size_t)(tok0 + row) * Cdim + kt + fC * 8);
        }
        CP_COMMIT();
    };

    fill(0, 0);
    fill(1, 1);

    for (int it = 0; it < 6; it++) {
        if (it < 5) CP_WAIT1(); else CP_WAIT0();
        __syncthreads();
        {
            const uint32_t bA = sbase + (uint32_t)(it % 3) * 32768u;
            const uint32_t bB = bA + 16384u;
#pragma unroll
            for (int ks = 0; ks < 4; ks++) {
                uint32_t a[4][4], b[4][4];
#pragma unroll
                for (int mt = 0; mt < 4; mt++)
                    ldsm4(a[mt], bA + sw128r(aRow[mt], ks * 2 + ldCh));
#pragma unroll
                for (int p = 0; p < 4; p++)
                    ldsm4(b[p], bB + sw128r(bRow[p], ks * 2 + ldCh));
#pragma unroll
                for (int mt = 0; mt < 4; mt++)
#pragma unroll
                    for (int p = 0; p < 4; p++) {
                        mma_f16(acc[mt][2 * p],     a[mt], b[p][0], b[p][2]);
                        mma_f16(acc[mt][2 * p + 1], a[mt], b[p][1], b[p][3]);
                    }
            }
        }
        if (it + 2 < 6) fill((it + 2) % 3, it + 2);
    }

    const int gid = lane >> 2, tig = lane & 3;
    float* outb = out + (size_t)(tok0 >> 12) * Cdim * Ndim;
    const int nb = (tok0 & 4095) + warp_n * 64 + 2 * tig;
#pragma unroll
    for (int mt = 0; mt < 4; mt++) {
        int r = j0 + warp_m * 64 + mt * 16 + gid;
        float bi0 = __ldg(&bias[r]), bi1 = __ldg(&bias[r + 8]);
#pragma unroll
        for (int nt = 0; nt < 8; nt++) {
            int cc = nb + nt * 8;
            *(float2*)(&outb[(size_t)r * Ndim + cc]) =
                make_float2(acc[mt][nt][0] + bi0, acc[mt][nt][1] + bi0);
            *(float2*)(&outb[(size_t)(r + 8) * Ndim + cc]) =
                make_float2(acc[mt][nt][2] + bi1, acc[mt][nt][3] + bi1);
        }
    }
}

// ---------------------------------------------------------------------------
extern "C" void kernel_launch(void* const* d_in, const int* in_sizes, int n_in,
                              void* d_out, int out_size) {
    const float* x      = (const float*)d_in[0];
    const float* qkv_w  = (const float*)d_in[1];
    const float* proj_w = (const float*)d_in[2];
    const float* proj_b = (const float*)d_in[3];
    float* out = (float*)d_out;

    const int smem_qkv  = 3 * (int)QKV_STAGE;   // 47616
    const int smem_gemm = 98304;
    const int smem_attn = 26624;
    cudaFuncSetAttribute(qkv_mma,  cudaFuncAttributeMaxDynamicSharedMemorySize, smem_qkv);
    cudaFuncSetAttribute(proj_mma, cudaFuncAttributeMaxDynamicSharedMemorySize, smem_gemm);
    cudaFuncSetAttribute(attn_mma, cudaFuncAttributeMaxDynamicSharedMemorySize, smem_attn);

    const size_t n4 = (size_t)Bq * Cdim * Ndim / 4 + (size_t)OC * Cdim / 4
                    + (size_t)Cdim * Cdim / 4;
    cvt_inputs<<<(int)((n4 + 255) / 256), 256>>>(x, qkv_w, proj_w);
    qkv_mma<<<dim3(12, 512), 128, smem_qkv>>>();
    attn_mma<<<8192, 128, smem_attn>>>();
    proj_mma<<<dim3(3, 512), 128, smem_gemm>>>(proj_b, out);
}

// round 16
// speedup vs baseline: 1.4017x; 1.0753x over previous
#include <cuda_runtime.h>
#include <cuda_fp16.h>
#include <cstdint>

#define Bq    16
#define Cdim  384
#define Ndim  4096
#define NH    8
#define HD    48
#define OC    1152
#define TOK   65536

// Scratch (__device__ globals: allocation-free rule)
__device__ __half g_xh[(size_t)Bq * Cdim * Ndim];  // fp16 copy of x  [B][C][N]
__device__ __half g_wq[OC * Cdim];                 // fp16 qkv_w
__device__ __half g_wp[Cdim * Cdim];               // fp16 proj_w
// blocked qkv: [(b*64+nc)*8+h][sel(3)][d(48)][tok64] — 18KB contiguous per attn block
__device__ __half g_qkvB[(size_t)Bq * 64 * NH * 3 * HD * 64];
__device__ __half g_attn[(size_t)TOK * Cdim];      // [tokens][C]

// ---------------------------------------------------------------------------
// helpers
// ---------------------------------------------------------------------------
__device__ __forceinline__ uint32_t smem_u32(const void* p) {
    uint32_t a; asm("{ .reg .u64 t; cvta.to.shared.u64 t, %1; cvt.u32.u64 %0, t; }" : "=r"(a) : "l"(p));
    return a;
}
__device__ __forceinline__ void ldsm4(uint32_t* r, uint32_t addr) {
    asm volatile("ldmatrix.sync.aligned.m8n8.x4.shared.b16 {%0,%1,%2,%3}, [%4];"
                 : "=r"(r[0]), "=r"(r[1]), "=r"(r[2]), "=r"(r[3]) : "r"(addr));
}
__device__ __forceinline__ void ldsm4t(uint32_t* r, uint32_t addr) {
    asm volatile("ldmatrix.sync.aligned.m8n8.x4.trans.shared.b16 {%0,%1,%2,%3}, [%4];"
                 : "=r"(r[0]), "=r"(r[1]), "=r"(r[2]), "=r"(r[3]) : "r"(addr));
}
__device__ __forceinline__ void mma_f16(float* d, const uint32_t* a, const uint32_t b0,
                                        const uint32_t b1) {
    asm volatile("mma.sync.aligned.m16n8k16.row.col.f32.f16.f16.f32 "
                 "{%0,%1,%2,%3}, {%4,%5,%6,%7}, {%8,%9}, {%0,%1,%2,%3};"
                 : "+f"(d[0]), "+f"(d[1]), "+f"(d[2]), "+f"(d[3])
                 : "r"(a[0]), "r"(a[1]), "r"(a[2]), "r"(a[3]), "r"(b0), "r"(b1));
}
__device__ __forceinline__ uint32_t sw128r(int row, int chunk) {
    return (uint32_t)(row * 128 + ((chunk ^ (row & 7)) << 4));
}
__device__ __forceinline__ uint32_t sw256r(int row, int chunk) {
    return (uint32_t)(row * 256 + ((chunk ^ (row & 7)) << 4));
}
__device__ __forceinline__ uint32_t pack2(float x, float y) {
    uint32_t r;
    asm("cvt.rn.f16x2.f32 %0, %1, %2;" : "=r"(r) : "f"(y), "f"(x));
    return r;
}
#define CP_ASYNC16(dst, src) \
    asm volatile("cp.async.cg.shared.global [%0], [%1], 16;" :: "r"(dst), "l"(src))
#define CP_COMMIT() asm volatile("cp.async.commit_group;" ::: "memory")
#define CP_WAIT1()  asm volatile("cp.async.wait_group 1;" ::: "memory")
#define CP_WAIT0()  asm volatile("cp.async.wait_group 0;" ::: "memory")

// ---------------------------------------------------------------------------
// Kernel 0: fp32 -> fp16 conversion, 4 float4 per thread (MLP=4).
// N4x = 6291456 = 6144*1024; N4q = 110592 = 108*1024; N4p = 36864 = 36*1024.
// grid = 6288 blocks x 256 thr, each block converts 1024 float4s.
// ---------------------------------------------------------------------------
__global__ __launch_bounds__(256) void cvt_inputs(const float* __restrict__ x,
                                                  const float* __restrict__ wq,
                                                  const float* __restrict__ wp) {
    const int tid = threadIdx.x;
    const int bx = blockIdx.x;
    const float4* src;
    uint2* dst;
    size_t base;
    if (bx < 6144) {
        src = (const float4*)x;  dst = (uint2*)g_xh;
        base = (size_t)bx * 1024 + tid;
    } else if (bx < 6252) {
        src = (const float4*)wq; dst = (uint2*)g_wq;
        base = (size_t)(bx - 6144) * 1024 + tid;
    } else {
        src = (const float4*)wp; dst = (uint2*)g_wp;
        base = (size_t)(bx - 6252) * 1024 + tid;
    }
    float4 v[4];
#pragma unroll
    for (int u = 0; u < 4; u++) v[u] = src[base + u * 256];
#pragma unroll
    for (int u = 0; u < 4; u++)
        dst[base + u * 256] = make_uint2(pack2(v[u].x, v[u].y), pack2(v[u].z, v[u].w));
}

// ---------------------------------------------------------------------------
// Kernel 1: qkv GEMM -> blocked layout g_qkvB.
// 128 thr, CTA tile 128x128, BK=64, warp tile 64x64 (2x2), cp.async 3-stage.
// ---------------------------------------------------------------------------
__global__ __launch_bounds__(128, 2) void qkv_mma() {
    extern __shared__ char smem[];
    const uint32_t sbase = smem_u32(smem);
    const int tid = threadIdx.x, lane = tid & 31, wid = tid >> 5;
    const int warp_m = wid >> 1, warp_n = wid & 1;
    const int j0 = blockIdx.x * 128;
    const int tok0 = blockIdx.y * 128;
    const int n0 = tok0 & 4095;
    const __half* xb = g_xh + (size_t)(tok0 >> 12) * Cdim * Ndim;

    const int aRowL = ((lane >> 3) & 1) * 8 + (lane & 7);
    const int ldCh = lane >> 4;
    int aRow[4];
#pragma unroll
    for (int mt = 0; mt < 4; mt++) aRow[mt] = warp_m * 64 + mt * 16 + aRowL;

    float acc[4][8][4];
#pragma unroll
    for (int i = 0; i < 4; i++)
#pragma unroll
        for (int j = 0; j < 8; j++)
#pragma unroll
            for (int q = 0; q < 4; q++) acc[i][j][q] = 0.f;

    const int aFr = tid >> 3, aFc = tid & 7;
    const int bFr = tid >> 4, bFc = tid & 15;

    auto fill = [&](int s, int t) {
        const int kt = t * 64;
        const uint32_t A = sbase + (uint32_t)s * 32768u;
        const uint32_t B = A + 16384u;
#pragma unroll
        for (int u = 0; u < 8; u++) {
            int row = aFr + u * 16;
            CP_ASYNC16(A + sw128r(row, aFc), g_wq + (size_t)(j0 + row) * Cdim + kt + aFc * 8);
        }
#pragma unroll
        for (int u = 0; u < 8; u++) {
            int krow = bFr + u * 8;
            CP_ASYNC16(B + sw256r(krow, bFc), xb + (size_t)(kt + krow) * Ndim + n0 + bFc * 8);
        }
        CP_COMMIT();
    };

    fill(0, 0);
    fill(1, 1);

    for (int it = 0; it < 6; it++) {
        if (it < 5) CP_WAIT1(); else CP_WAIT0();
        __syncthreads();
        {
            const uint32_t bA = sbase + (uint32_t)(it % 3) * 32768u;
            const uint32_t bB = bA + 16384u;
            uint32_t a[2][4][4], b[2][4][4];
#pragma unroll
            for (int mt = 0; mt < 4; mt++)
                ldsm4(a[0][mt], bA + sw128r(aRow[mt], ldCh));
#pragma unroll
            for (int p = 0; p < 4; p++)
                ldsm4t(b[0][p], bB + sw256r(aRowL, warp_n * 8 + p * 2 + ldCh));
#pragma unroll
            for (int ks = 0; ks < 4; ks++) {
                const int cur = ks & 1, nxt = cur ^ 1;
                if (ks < 3) {
#pragma unroll
                    for (int mt = 0; mt < 4; mt++)
                        ldsm4(a[nxt][mt], bA + sw128r(aRow[mt], (ks + 1) * 2 + ldCh));
#pragma unroll
                    for (int p = 0; p < 4; p++)
                        ldsm4t(b[nxt][p], bB + sw256r((ks + 1) * 16 + aRowL,
                                                      warp_n * 8 + p * 2 + ldCh));
                }
#pragma unroll
                for (int mt = 0; mt < 4; mt++)
#pragma unroll
                    for (int p = 0; p < 4; p++) {
                        mma_f16(acc[mt][2 * p],     a[cur][mt], b[cur][p][0], b[cur][p][1]);
                        mma_f16(acc[mt][2 * p + 1], a[cur][mt], b[cur][p][2], b[cur][p][3]);
                    }
            }
        }
        if (it + 2 < 6) fill((it + 2) % 3, it + 2);
    }

    // epilogue: scatter into blocked layout
    const int gid = lane >> 2, tig = lane & 3;
    const int bq  = tok0 >> 12;
    const int ncq = ((tok0 & 4095) >> 6) + warp_n;
    const size_t chunkbase = (size_t)((bq * 64 + ncq) * NH) * (3 * HD * 64);
#pragma unroll
    for (int mt = 0; mt < 4; mt++) {
        int rb = j0 + warp_m * 64 + mt * 16 + gid;
#pragma unroll
        for (int rr2 = 0; rr2 < 2; rr2++) {
            int r = rb + rr2 * 8;
            int sel = r / 384;
            int rm = r - sel * 384;
            int h = rm / 48;
            int d = rm - h * 48;
            size_t rowbase = chunkbase + (size_t)((h * 3 + sel) * (HD * 64) + d * 64);
#pragma unroll
            for (int nt = 0; nt < 8; nt++) {
                int t64 = nt * 8 + 2 * tig;
                *(uint32_t*)(&g_qkvB[rowbase + t64]) =
                    pack2(acc[mt][nt][2 * rr2], acc[mt][nt][2 * rr2 + 1]);
            }
        }
    }
}

// ---------------------------------------------------------------------------
// Kernel 2: block-local attention, fp16 mma. 1 CTA (128 thr) per chunk-block.
// ---------------------------------------------------------------------------
__global__ __launch_bounds__(128) void attn_mma() {
    extern __shared__ char smem[];
    const uint32_t sbase = smem_u32(smem);
    const int tid = threadIdx.x, lane = tid & 31, w = tid >> 5;
    const int blk = blockIdx.x;                 // (b*64+nc)*8 + h
    const int b = blk >> 9, nc = (blk >> 3) & 63, h = blk & 7;
    const size_t m0 = (size_t)b * Ndim + nc * 64;
    const char* gsrc = (const char*)(g_qkvB) + (size_t)blk * (3 * HD * 64 * 2);

#pragma unroll
    for (int u = 0; u < 9; u++) {
        int ci = tid + u * 128;
        int row = ci >> 3, c8 = ci & 7;
        CP_ASYNC16(sbase + sw128r(row, c8), gsrc + (size_t)ci * 16);
    }
    CP_COMMIT(); CP_WAIT0();
    __syncthreads();

    const int aRowL = ((lane >> 3) & 1) * 8 + (lane & 7);
    const int ldCh = lane >> 4;

    float s[8][4];
#pragma unroll
    for (int j = 0; j < 8; j++)
#pragma unroll
        for (int q = 0; q < 4; q++) s[j][q] = 0.f;
#pragma unroll
    for (int ks = 0; ks < 3; ks++) {
        uint32_t ar[4], a[4], kb[4][4];
        int drow = ks * 16 + aRowL;
        ldsm4t(ar, sbase + sw128r(drow, w * 2 + ldCh));
        a[0] = ar[0]; a[1] = ar[2]; a[2] = ar[1]; a[3] = ar[3];
#pragma unroll
        for (int p = 0; p < 4; p++)
            ldsm4t(kb[p], sbase + 6144u + sw128r(drow, p * 2 + ldCh));
#pragma unroll
        for (int p = 0; p < 4; p++) {
            mma_f16(s[2 * p],     a, kb[p][0], kb[p][1]);
            mma_f16(s[2 * p + 1], a, kb[p][2], kb[p][3]);
        }
    }

    const int gid = lane >> 2, tig = lane & 3;
    const float scale = 0.14433756729740643f;
    {
        float m0v = -1e30f, m1v = -1e30f;
#pragma unroll
        for (int nt = 0; nt < 8; nt++) {
#pragma unroll
            for (int q = 0; q < 4; q++) s[nt][q] *= scale;
            m0v = fmaxf(m0v, fmaxf(s[nt][0], s[nt][1]));
            m1v = fmaxf(m1v, fmaxf(s[nt][2], s[nt][3]));
        }
#pragma unroll
        for (int o = 1; o <= 2; o <<= 1) {
            m0v = fmaxf(m0v, __shfl_xor_sync(~0u, m0v, o));
            m1v = fmaxf(m1v, __shfl_xor_sync(~0u, m1v, o));
        }
        float s0 = 0.f, s1 = 0.f;
#pragma unroll
        for (int nt = 0; nt < 8; nt++) {
            s[nt][0] = __expf(s[nt][0] - m0v); s[nt][1] = __expf(s[nt][1] - m0v);
            s[nt][2] = __expf(s[nt][2] - m1v); s[nt][3] = __expf(s[nt][3] - m1v);
            s0 += s[nt][0] + s[nt][1]; s1 += s[nt][2] + s[nt][3];
        }
#pragma unroll
        for (int o = 1; o <= 2; o <<= 1) {
            s0 += __shfl_xor_sync(~0u, s0, o);
            s1 += __shfl_xor_sync(~0u, s1, o);
        }
        float i0 = 1.f / s0, i1 = 1.f / s1;
        const int r0 = w * 16 + gid, r1 = r0 + 8;
        char* Ps = smem + 18432;
#pragma unroll
        for (int nt = 0; nt < 8; nt++) {
            *(uint32_t*)(Ps + sw128r(r0, nt) + tig * 4) = pack2(s[nt][0] * i0, s[nt][1] * i0);
            *(uint32_t*)(Ps + sw128r(r1, nt) + tig * 4) = pack2(s[nt][2] * i1, s[nt][3] * i1);
        }
    }
    __syncwarp();

    float o[6][4];
#pragma unroll
    for (int j = 0; j < 6; j++)
#pragma unroll
        for (int q = 0; q < 4; q++) o[j][q] = 0.f;
#pragma unroll
    for (int ks = 0; ks < 4; ks++) {
        uint32_t a[4], vb[3][4];
        ldsm4(a, sbase + 18432u + sw128r(w * 16 + aRowL, ks * 2 + ldCh));
#pragma unroll
        for (int p = 0; p < 3; p++)
            ldsm4(vb[p], sbase + 12288u + sw128r(p * 16 + aRowL, ks * 2 + ldCh));
#pragma unroll
        for (int p = 0; p < 3; p++) {
            mma_f16(o[2 * p],     a, vb[p][0], vb[p][2]);
            mma_f16(o[2 * p + 1], a, vb[p][1], vb[p][3]);
        }
    }
    {
        const int r0 = w * 16 + gid;
#pragma unroll
        for (int nt = 0; nt < 6; nt++) {
            int col = h * HD + nt * 8 + tig * 2;
            *(uint32_t*)(&g_attn[(m0 + r0) * Cdim + col])     = pack2(o[nt][0], o[nt][1]);
            *(uint32_t*)(&g_attn[(m0 + r0 + 8) * Cdim + col]) = pack2(o[nt][2], o[nt][3]);
        }
    }
}

// ---------------------------------------------------------------------------
// Kernel 3: out[b][c][n] = sum_k g_wp[c][k] * g_attn[tok][k] + bias[c]
// 128 thr, warp tile 64x64 (2x2), cp.async 3-stage.
// ---------------------------------------------------------------------------
__global__ __launch_bounds__(128, 2) void proj_mma(const float* __restrict__ bias,
                                                   float* __restrict__ out) {
    extern __shared__ char smem[];
    const uint32_t sbase = smem_u32(smem);
    const int tid = threadIdx.x, lane = tid & 31, wid = tid >> 5;
    const int warp_m = wid >> 1, warp_n = wid & 1;
    const int j0 = blockIdx.x * 128;
    const int tok0 = blockIdx.y * 128;

    const int aRowL = ((lane >> 3) & 1) * 8 + (lane & 7);
    const int ldCh = lane >> 4;
    int aRow[4], bRow[4];
#pragma unroll
    for (int mt = 0; mt < 4; mt++) aRow[mt] = warp_m * 64 + mt * 16 + aRowL;
#pragma unroll
    for (int p = 0; p < 4; p++)    bRow[p] = warp_n * 64 + p * 16 + aRowL;

    float acc[4][8][4];
#pragma unroll
    for (int i = 0; i < 4; i++)
#pragma unroll
        for (int j = 0; j < 8; j++)
#pragma unroll
            for (int q = 0; q < 4; q++) acc[i][j][q] = 0.f;

    const int fR = tid >> 3, fC = tid & 7;
    auto fill = [&](int s, int t) {
        const int kt = t * 64;
        const uint32_t A = sbase + (uint32_t)s * 32768u;
        const uint32_t B = A + 16384u;
#pragma unroll
        for (int u = 0; u < 8; u++) {
            int row = fR + u * 16;
            CP_ASYNC16(A + sw128r(row, fC), g_wp + (size_t)(j0 + row) * Cdim + kt + fC * 8);
            CP_ASYNC16(B + sw128r(row, fC),
                       g_attn + (size_t)(tok0 + row) * Cdim + kt + fC * 8);
        }
        CP_COMMIT();
    };

    fill(0, 0);
    fill(1, 1);

    for (int it = 0; it < 6; it++) {
        if (it < 5) CP_WAIT1(); else CP_WAIT0();
        __syncthreads();
        {
            const uint32_t bA = sbase + (uint32_t)(it % 3) * 32768u;
            const uint32_t bB = bA + 16384u;
            uint32_t a[2][4][4], b[2][4][4];
#pragma unroll
            for (int mt = 0; mt < 4; mt++)
                ldsm4(a[0][mt], bA + sw128r(aRow[mt], ldCh));
#pragma unroll
            for (int p = 0; p < 4; p++)
                ldsm4(b[0][p], bB + sw128r(bRow[p], ldCh));
#pragma unroll
            for (int ks = 0; ks < 4; ks++) {
                const int cur = ks & 1, nxt = cur ^ 1;
                if (ks < 3) {
#pragma unroll
                    for (int mt = 0; mt < 4; mt++)
                        ldsm4(a[nxt][mt], bA + sw128r(aRow[mt], (ks + 1) * 2 + ldCh));
#pragma unroll
                    for (int p = 0; p < 4; p++)
                        ldsm4(b[nxt][p], bB + sw128r(bRow[p], (ks + 1) * 2 + ldCh));
                }
#pragma unroll
                for (int mt = 0; mt < 4; mt++)
#pragma unroll
                    for (int p = 0; p < 4; p++) {
                        mma_f16(acc[mt][2 * p],     a[cur][mt], b[cur][p][0], b[cur][p][2]);
                        mma_f16(acc[mt][2 * p + 1], a[cur][mt], b[cur][p][1], b[cur][p][3]);
                    }
            }
        }
        if (it + 2 < 6) fill((it + 2) % 3, it + 2);
    }

    const int gid = lane >> 2, tig = lane & 3;
    float* outb = out + (size_t)(tok0 >> 12) * Cdim * Ndim;
    const int nb = (tok0 & 4095) + warp_n * 64 + 2 * tig;
#pragma unroll
    for (int mt = 0; mt < 4; mt++) {
        int r = j0 + warp_m * 64 + mt * 16 + gid;
        float bi0 = __ldg(&bias[r]), bi1 = __ldg(&bias[r + 8]);
#pragma unroll
        for (int nt = 0; nt < 8; nt++) {
            int cc = nb + nt * 8;
            *(float2*)(&outb[(size_t)r * Ndim + cc]) =
                make_float2(acc[mt][nt][0] + bi0, acc[mt][nt][1] + bi0);
            *(float2*)(&outb[(size_t)(r + 8) * Ndim + cc]) =
                make_float2(acc[mt][nt][2] + bi1, acc[mt][nt][3] + bi1);
        }
    }
}

// ---------------------------------------------------------------------------
extern "C" void kernel_launch(void* const* d_in, const int* in_sizes, int n_in,
                              void* d_out, int out_size) {
    const float* x      = (const float*)d_in[0];
    const float* qkv_w  = (const float*)d_in[1];
    const float* proj_w = (const float*)d_in[2];
    const float* proj_b = (const float*)d_in[3];
    float* out = (float*)d_out;

    const int smem_gemm = 98304;   // 3 stages x 32KB
    const int smem_attn = 26624;   // QKV 18KB + P 8KB
    cudaFuncSetAttribute(qkv_mma,  cudaFuncAttributeMaxDynamicSharedMemorySize, smem_gemm);
    cudaFuncSetAttribute(proj_mma, cudaFuncAttributeMaxDynamicSharedMemorySize, smem_gemm);
    cudaFuncSetAttribute(attn_mma, cudaFuncAttributeMaxDynamicSharedMemorySize, smem_attn);

    cvt_inputs<<<6288, 256>>>(x, qkv_w, proj_w);
    qkv_mma<<<dim3(9, 512), 128, smem_gemm>>>();
    attn_mma<<<8192, 128, smem_attn>>>();
    proj_mma<<<dim3(3, 512), 128, smem_gemm>>>(proj_b, out);
}